// round 8
// baseline (speedup 1.0000x reference)
#include <cuda_runtime.h>
#include <cuda_fp16.h>
#include <stdint.h>
#include <math.h>

// ---------------------------------------------------------------------------
// Problem dims
// ---------------------------------------------------------------------------
#define B_SZ   16384
#define D_IN   1280
#define D_HID  512
#define D_OUT  229
#define K1     (7 * D_IN)    // 8960
#define K2     (7 * D_HID)   // 3584
#define N2PAD  256

// ---------------------------------------------------------------------------
// Scratch
// ---------------------------------------------------------------------------
static __device__ __half g_A1[(size_t)B_SZ * K1];
static __device__ __half g_W1[(size_t)D_HID * K1];
static __device__ float  g_h [(size_t)B_SZ * D_HID];
static __device__ __half g_A2[(size_t)B_SZ * K2];
static __device__ __half g_W2[(size_t)N2PAD * K2];

// ---------------------------------------------------------------------------
// Closed-form uniform cubic B-spline bases (== reference Cox-de Boor on the
// uniform knot vector t_j = -1 + (j-3)*2/3, j=0..9).
// cell c = floor((x+3)*1.5) in [0,8]; u = frac. Active bases j = c-3..c.
// ---------------------------------------------------------------------------
__device__ __forceinline__ void kan_bases_cf(float x, float bs[6]) {
#pragma unroll
    for (int j = 0; j < 6; ++j) bs[j] = 0.0f;
    float s = (x + 3.0f) * 1.5f;
    float cf = floorf(s);
    int c = (int)cf;
    if (c < 0 || c > 8) return;
    float u  = s - cf;
    float u2 = u * u;
    float u3 = u2 * u;
    float om = 1.0f - u;
    float seg0 = om * om * om * (1.0f / 6.0f);
    float seg1 = (3.0f * u3 - 6.0f * u2 + 4.0f) * (1.0f / 6.0f);
    float seg2 = (-3.0f * u3 + 3.0f * u2 + 3.0f * u + 1.0f) * (1.0f / 6.0f);
    float seg3 = u3 * (1.0f / 6.0f);
#pragma unroll
    for (int k = 0; k < 4; ++k) {
        int j = c - 3 + k;
        float v = (k == 0) ? seg0 : (k == 1) ? seg1 : (k == 2) ? seg2 : seg3;
        if (j >= 0 && j < 6) bs[j] = v;
    }
}

__device__ __forceinline__ float silu_f(float v) { return v / (1.0f + expf(-v)); }

__device__ __forceinline__ uint32_t pk2(float a, float b) {
    __half2 h = __floats2half2_rn(a, b);
    return *reinterpret_cast<uint32_t*>(&h);
}

// ---------------------------------------------------------------------------
// Merged prep kernel: expand1 + fusew1 + fusew2. 8 elements per thread,
// all global stores are 16B uint4, all x/weight loads float4.
// ---------------------------------------------------------------------------
#define E1_BLOCKS (B_SZ * (D_IN / 8) / 256)     // 10240
#define F1_BLOCKS (D_HID * (D_IN / 8) / 256)    // 320
#define F2_BLOCKS (N2PAD * (D_HID / 8) / 256)   // 64
#define PREP_BLOCKS (E1_BLOCKS + F1_BLOCKS + F2_BLOCKS)

__global__ __launch_bounds__(256) void prep_kernel(
    const float* __restrict__ x,
    const float* __restrict__ bw1, const float* __restrict__ sw1,
    const float* __restrict__ sc1,
    const float* __restrict__ bw2, const float* __restrict__ sw2,
    const float* __restrict__ sc2)
{
    const int blk = blockIdx.x;
    if (blk < E1_BLOCKS) {
        // ---- expand1: 8 consecutive features per thread ----
        int idx = blk * 256 + threadIdx.x;          // over B_SZ * 160
        int b  = idx / (D_IN / 8);
        int i8 = (idx - b * (D_IN / 8)) * 8;
        const float* xp = x + (size_t)b * D_IN + i8;
        float4 va = *reinterpret_cast<const float4*>(xp);
        float4 vb = *reinterpret_cast<const float4*>(xp + 4);
        float v[8] = {va.x, va.y, va.z, va.w, vb.x, vb.y, vb.z, vb.w};
        float sl[8];
        float bs[8][6];
#pragma unroll
        for (int e = 0; e < 8; ++e) {
            sl[e] = silu_f(v[e]);
            kan_bases_cf(v[e], bs[e]);
        }
        __half* dst = g_A1 + (size_t)b * K1 + i8;
        uint4 r;
        r.x = pk2(sl[0], sl[1]); r.y = pk2(sl[2], sl[3]);
        r.z = pk2(sl[4], sl[5]); r.w = pk2(sl[6], sl[7]);
        *reinterpret_cast<uint4*>(dst) = r;
#pragma unroll
        for (int j = 0; j < 6; ++j) {
            r.x = pk2(bs[0][j], bs[1][j]); r.y = pk2(bs[2][j], bs[3][j]);
            r.z = pk2(bs[4][j], bs[5][j]); r.w = pk2(bs[6][j], bs[7][j]);
            *reinterpret_cast<uint4*>(dst + (size_t)(j + 1) * D_IN) = r;
        }
    } else if (blk < E1_BLOCKS + F1_BLOCKS) {
        // ---- fusew1: 8 consecutive input features per thread ----
        int idx = (blk - E1_BLOCKS) * 256 + threadIdx.x;   // over D_HID * 160
        int o  = idx / (D_IN / 8);
        int i8 = (idx - o * (D_IN / 8)) * 8;
        const size_t w0 = (size_t)o * D_IN + i8;
        float4 ba = *reinterpret_cast<const float4*>(bw1 + w0);
        float4 bb = *reinterpret_cast<const float4*>(bw1 + w0 + 4);
        float4 sa = *reinterpret_cast<const float4*>(sc1 + w0);
        float4 sb = *reinterpret_cast<const float4*>(sc1 + w0 + 4);
        float sc[8] = {sa.x, sa.y, sa.z, sa.w, sb.x, sb.y, sb.z, sb.w};
        __half* dst = g_W1 + (size_t)o * K1 + i8;
        uint4 r;
        r.x = pk2(ba.x, ba.y); r.y = pk2(ba.z, ba.w);
        r.z = pk2(bb.x, bb.y); r.w = pk2(bb.z, bb.w);
        *reinterpret_cast<uint4*>(dst) = r;
#pragma unroll
        for (int j = 0; j < 6; ++j) {
            float f[8];
#pragma unroll
            for (int e = 0; e < 8; ++e)
                f[e] = sw1[(w0 + e) * 6 + j] * sc[e];
            r.x = pk2(f[0], f[1]); r.y = pk2(f[2], f[3]);
            r.z = pk2(f[4], f[5]); r.w = pk2(f[6], f[7]);
            *reinterpret_cast<uint4*>(dst + (size_t)(j + 1) * D_IN) = r;
        }
    } else {
        // ---- fusew2 (zero-padded rows o >= D_OUT): 8 cols per thread ----
        int idx = (blk - E1_BLOCKS - F1_BLOCKS) * 256 + threadIdx.x;  // N2PAD*64
        int o  = idx / (D_HID / 8);
        int c8 = (idx - o * (D_HID / 8)) * 8;
        __half* dst = g_W2 + (size_t)o * K2 + c8;
        if (o < D_OUT) {
            const size_t w0 = (size_t)o * D_HID + c8;
            float4 ba = *reinterpret_cast<const float4*>(bw2 + w0);
            float4 bb = *reinterpret_cast<const float4*>(bw2 + w0 + 4);
            float4 sa = *reinterpret_cast<const float4*>(sc2 + w0);
            float4 sb = *reinterpret_cast<const float4*>(sc2 + w0 + 4);
            float sc[8] = {sa.x, sa.y, sa.z, sa.w, sb.x, sb.y, sb.z, sb.w};
            uint4 r;
            r.x = pk2(ba.x, ba.y); r.y = pk2(ba.z, ba.w);
            r.z = pk2(bb.x, bb.y); r.w = pk2(bb.z, bb.w);
            *reinterpret_cast<uint4*>(dst) = r;
#pragma unroll
            for (int j = 0; j < 6; ++j) {
                float f[8];
#pragma unroll
                for (int e = 0; e < 8; ++e)
                    f[e] = sw2[(w0 + e) * 6 + j] * sc[e];
                r.x = pk2(f[0], f[1]); r.y = pk2(f[2], f[3]);
                r.z = pk2(f[4], f[5]); r.w = pk2(f[6], f[7]);
                *reinterpret_cast<uint4*>(dst + (size_t)(j + 1) * D_HID) = r;
            }
        } else {
            uint4 z = {0u, 0u, 0u, 0u};
            *reinterpret_cast<uint4*>(dst) = z;
#pragma unroll
            for (int j = 0; j < 6; ++j)
                *reinterpret_cast<uint4*>(dst + (size_t)(j + 1) * D_HID) = z;
        }
    }
}

// ---------------------------------------------------------------------------
// LayerNorm + expansion: ONE WARP PER ROW (no __syncthreads).
// Thread handles 16 consecutive cols; float4 loads, 16B packed stores.
// ---------------------------------------------------------------------------
__global__ __launch_bounds__(256) void ln_expand2_kernel(
    const float* __restrict__ gamma, const float* __restrict__ beta)
{
    const int warp = threadIdx.x >> 5;
    const int lane = threadIdx.x & 31;
    const int row  = blockIdx.x * 8 + warp;
    const int c0   = lane * 16;

    const float* hr = g_h + (size_t)row * D_HID + c0;
    float v[16];
#pragma unroll
    for (int q = 0; q < 4; ++q) {
        float4 t = *reinterpret_cast<const float4*>(hr + q * 4);
        v[q * 4 + 0] = t.x; v[q * 4 + 1] = t.y;
        v[q * 4 + 2] = t.z; v[q * 4 + 3] = t.w;
    }
    float s = 0.0f, q2 = 0.0f;
#pragma unroll
    for (int i = 0; i < 16; ++i) { s += v[i]; q2 += v[i] * v[i]; }
#pragma unroll
    for (int o = 16; o; o >>= 1) {
        s  += __shfl_xor_sync(0xffffffffu, s, o);
        q2 += __shfl_xor_sync(0xffffffffu, q2, o);
    }
    const float mean = s * (1.0f / (float)D_HID);
    const float var  = q2 * (1.0f / (float)D_HID) - mean * mean;
    const float inv  = rsqrtf(var + 1e-5f);

    float ga[16], be[16];
#pragma unroll
    for (int q = 0; q < 4; ++q) {
        float4 t = *reinterpret_cast<const float4*>(gamma + c0 + q * 4);
        ga[q * 4 + 0] = t.x; ga[q * 4 + 1] = t.y;
        ga[q * 4 + 2] = t.z; ga[q * 4 + 3] = t.w;
        float4 u = *reinterpret_cast<const float4*>(beta + c0 + q * 4);
        be[q * 4 + 0] = u.x; be[q * 4 + 1] = u.y;
        be[q * 4 + 2] = u.z; be[q * 4 + 3] = u.w;
    }

    uint32_t out[7][8];
#pragma unroll
    for (int e2 = 0; e2 < 8; ++e2) {
        float y0 = (v[e2 * 2]     - mean) * inv * ga[e2 * 2]     + be[e2 * 2];
        float y1 = (v[e2 * 2 + 1] - mean) * inv * ga[e2 * 2 + 1] + be[e2 * 2 + 1];
        float b0[6], b1[6];
        kan_bases_cf(y0, b0);
        kan_bases_cf(y1, b1);
        out[0][e2] = pk2(silu_f(y0), silu_f(y1));
#pragma unroll
        for (int j = 0; j < 6; ++j)
            out[j + 1][e2] = pk2(b0[j], b1[j]);
    }

    __half* dst = g_A2 + (size_t)row * K2 + c0;
#pragma unroll
    for (int j = 0; j < 7; ++j) {
        uint4 r0 = {out[j][0], out[j][1], out[j][2], out[j][3]};
        uint4 r1 = {out[j][4], out[j][5], out[j][6], out[j][7]};
        __half* p = dst + (size_t)j * D_HID;
        *reinterpret_cast<uint4*>(p)     = r0;
        *reinterpret_cast<uint4*>(p + 8) = r1;
    }
}

// ---------------------------------------------------------------------------
// HMMA GEMM (unchanged R5/R7 config — at mma.sync ceiling):
// Block 128x128x64, 512 threads (16 warps = 4M x 4N), warp tile 32x32.
// 32 warps/SM at 2 CTAs/SM. 3-stage cp.async ring. 144B smem rows.
// ---------------------------------------------------------------------------
#define BM 128
#define BN 128
#define BK 64
#define ROWB 144u
#define STG_B (uint32_t)((BM + BN) * ROWB)   // 36864 B
#define NSTG 3

template <int L>
__global__ __launch_bounds__(512, 2) void gemm_hmma(float* __restrict__ Cparam) {
    constexpr int KK = (L == 1) ? K1 : K2;
    constexpr int NV = (L == 1) ? D_HID : D_OUT;
    constexpr int KT = KK / BK;

    const __half* __restrict__ A  = (L == 1) ? g_A1 : g_A2;
    const __half* __restrict__ Bw = (L == 1) ? g_W1 : g_W2;
    float* __restrict__ C         = (L == 1) ? g_h  : Cparam;

    extern __shared__ __half smh[];
    const uint32_t sbase = (uint32_t)__cvta_generic_to_shared(smh);

    const int tid  = threadIdx.x;
    const int warp = tid >> 5;
    const int lane = tid & 31;
    const int wm = (warp & 3) * 32;
    const int wn = (warp >> 2) * 32;
    const int mb = blockIdx.y;
    const int nb = blockIdx.x;

    const __half* Abase = A  + (size_t)(mb * BM) * KK;
    const __half* Bbase = Bw + (size_t)(nb * BN) * KK;

    auto issue = [&](int kt) {
        const uint32_t sb = sbase + (uint32_t)(kt % NSTG) * STG_B;
#pragma unroll
        for (int i = 0; i < 2; ++i) {
            const int idx = tid + i * 512;
            const int r = idx >> 3, c = idx & 7;
            const void* src = Abase + (size_t)r * KK + kt * BK + c * 8;
            const uint32_t dst = sb + (uint32_t)r * ROWB + (uint32_t)c * 16u;
            asm volatile("cp.async.cg.shared.global [%0], [%1], 16;"
                         :: "r"(dst), "l"(src));
        }
#pragma unroll
        for (int i = 0; i < 2; ++i) {
            const int idx = tid + i * 512;
            const int r = idx >> 3, c = idx & 7;
            const void* src = Bbase + (size_t)r * KK + kt * BK + c * 8;
            const uint32_t dst = sb + (uint32_t)BM * ROWB
                               + (uint32_t)r * ROWB + (uint32_t)c * 16u;
            asm volatile("cp.async.cg.shared.global [%0], [%1], 16;"
                         :: "r"(dst), "l"(src));
        }
        asm volatile("cp.async.commit_group;" ::: "memory");
    };

    float acc[2][4][4] = {};

    issue(0); issue(1);

    const int lrow = lane & 15;
    const int lcb  = (lane >> 4) * 8;

#pragma unroll 1
    for (int kt = 0; kt < KT; ++kt) {
        if (kt + 1 < KT) asm volatile("cp.async.wait_group 1;" ::: "memory");
        else             asm volatile("cp.async.wait_group 0;" ::: "memory");
        __syncthreads();
        if (kt + 2 < KT) issue(kt + 2);

        const uint32_t sb = sbase + (uint32_t)(kt % NSTG) * STG_B;
#pragma unroll
        for (int ks = 0; ks < 4; ++ks) {
            uint32_t a[2][4];
            uint32_t bq[2][4];
#pragma unroll
            for (int mt = 0; mt < 2; ++mt) {
                const uint32_t addr = sb + (uint32_t)(wm + mt * 16 + lrow) * ROWB
                                    + (uint32_t)(ks * 16 + lcb) * 2u;
                asm volatile("ldmatrix.sync.aligned.m8n8.x4.shared.b16 {%0,%1,%2,%3}, [%4];"
                             : "=r"(a[mt][0]), "=r"(a[mt][1]), "=r"(a[mt][2]), "=r"(a[mt][3])
                             : "r"(addr));
            }
#pragma unroll
            for (int np = 0; np < 2; ++np) {
                const uint32_t addr = sb + (uint32_t)BM * ROWB
                                    + (uint32_t)(wn + np * 16 + lrow) * ROWB
                                    + (uint32_t)(ks * 16 + lcb) * 2u;
                asm volatile("ldmatrix.sync.aligned.m8n8.x4.shared.b16 {%0,%1,%2,%3}, [%4];"
                             : "=r"(bq[np][0]), "=r"(bq[np][1]), "=r"(bq[np][2]), "=r"(bq[np][3])
                             : "r"(addr));
            }
#pragma unroll
            for (int mt = 0; mt < 2; ++mt) {
#pragma unroll
                for (int nt = 0; nt < 4; ++nt) {
                    const int np = nt >> 1, pp = nt & 1;
                    asm volatile(
                        "mma.sync.aligned.m16n8k16.row.col.f32.f16.f16.f32 "
                        "{%0,%1,%2,%3}, {%4,%5,%6,%7}, {%8,%9}, {%0,%1,%2,%3};"
                        : "+f"(acc[mt][nt][0]), "+f"(acc[mt][nt][1]),
                          "+f"(acc[mt][nt][2]), "+f"(acc[mt][nt][3])
                        : "r"(a[mt][0]), "r"(a[mt][1]), "r"(a[mt][2]), "r"(a[mt][3]),
                          "r"(bq[np][pp]), "r"(bq[np][pp + 2]));
                }
            }
        }
    }

    // ---- epilogue ----
    const int gr = lane >> 2;
    const int gc = (lane & 3) * 2;
#pragma unroll
    for (int mt = 0; mt < 2; ++mt) {
#pragma unroll
        for (int nt = 0; nt < 4; ++nt) {
            const int row = mb * BM + wm + mt * 16 + gr;
            const int col = nb * BN + wn + nt * 8 + gc;
            float* cp = C + (size_t)row * NV;
            if (NV % BN == 0) {
                cp[col]     = acc[mt][nt][0];
                cp[col + 1] = acc[mt][nt][1];
                cp += (size_t)8 * NV;
                cp[col]     = acc[mt][nt][2];
                cp[col + 1] = acc[mt][nt][3];
            } else {
                if (col < NV)     cp[col]     = acc[mt][nt][0];
                if (col + 1 < NV) cp[col + 1] = acc[mt][nt][1];
                cp += (size_t)8 * NV;
                if (col < NV)     cp[col]     = acc[mt][nt][2];
                if (col + 1 < NV) cp[col + 1] = acc[mt][nt][3];
            }
        }
    }
}

// ---------------------------------------------------------------------------
// Launch
// ---------------------------------------------------------------------------
#define GEMM_SMEM (NSTG * (int)STG_B)   // 110592 B

extern "C" void kernel_launch(void* const* d_in, const int* in_sizes, int n_in,
                              void* d_out, int out_size) {
    (void)in_sizes; (void)n_in; (void)out_size;
    const float* x   = (const float*)d_in[0];
    const float* bw1 = (const float*)d_in[1];
    const float* sw1 = (const float*)d_in[2];
    const float* sc1 = (const float*)d_in[3];
    const float* ga  = (const float*)d_in[4];
    const float* be  = (const float*)d_in[5];
    const float* bw2 = (const float*)d_in[6];
    const float* sw2 = (const float*)d_in[7];
    const float* sc2 = (const float*)d_in[8];
    float* out = (float*)d_out;

    cudaFuncSetAttribute(gemm_hmma<1>,
                         cudaFuncAttributeMaxDynamicSharedMemorySize, GEMM_SMEM);
    cudaFuncSetAttribute(gemm_hmma<2>,
                         cudaFuncAttributeMaxDynamicSharedMemorySize, GEMM_SMEM);

    prep_kernel<<<PREP_BLOCKS, 256>>>(x, bw1, sw1, sc1, bw2, sw2, sc2);

    // GEMM1: 512 CTAs (4 x 128)
    gemm_hmma<1><<<dim3(4, 128), 512, GEMM_SMEM>>>(nullptr);

    ln_expand2_kernel<<<B_SZ / 8, 256>>>(ga, be);

    // GEMM2: 256 CTAs (2 x 128)
    gemm_hmma<2><<<dim3(2, 128), 512, GEMM_SMEM>>>(out);
}

// round 9
// speedup vs baseline: 1.2907x; 1.2907x over previous
#include <cuda_runtime.h>
#include <cuda_fp16.h>
#include <stdint.h>
#include <math.h>

// ---------------------------------------------------------------------------
// Problem dims
// ---------------------------------------------------------------------------
#define B_SZ   16384
#define D_IN   1280
#define D_HID  512
#define D_OUT  229
#define K1     (7 * D_IN)    // 8960
#define K2     (7 * D_HID)   // 3584
#define N2PAD  256

// ---------------------------------------------------------------------------
// Scratch
// ---------------------------------------------------------------------------
static __device__ __half g_A1[(size_t)B_SZ * K1];
static __device__ __half g_W1[(size_t)D_HID * K1];
static __device__ float  g_h [(size_t)B_SZ * D_HID];
static __device__ __half g_A2[(size_t)B_SZ * K2];
static __device__ __half g_W2[(size_t)N2PAD * K2];

// ---------------------------------------------------------------------------
// Closed-form uniform cubic B-spline bases — STATIC indexing only (branchless
// select chain; no dynamically-indexed local array -> stays in registers).
// Equivalent to the reference Cox-de Boor recursion on knots t_j = -1+(j-3)*2/3:
// cell c = floor((x+3)*1.5); basis j gets seg(3-(c-j)) when c-j in [0,3].
// Verified numerically in R8 (rel_err unchanged); R8's version spilled to
// local memory via bs[dynamic] — this one cannot.
// ---------------------------------------------------------------------------
__device__ __forceinline__ void kan_bases(float x, float bs[6]) {
    const float s  = (x + 3.0f) * 1.5f;
    const float cf = floorf(s);
    const int   c  = (int)cf;
    const float u  = s - cf;
    const float u2 = u * u;
    const float u3 = u2 * u;
    const float om = 1.0f - u;
    const float seg0 = om * om * om * (1.0f / 6.0f);                          // c == j+3
    const float seg1 = (3.0f * u3 - 6.0f * u2 + 4.0f) * (1.0f / 6.0f);        // c == j+2
    const float seg2 = (-3.0f * u3 + 3.0f * u2 + 3.0f * u + 1.0f) * (1.0f / 6.0f); // c == j+1
    const float seg3 = u3 * (1.0f / 6.0f);                                    // c == j
#pragma unroll
    for (int j = 0; j < 6; ++j) {
        float v = 0.0f;
        v = (c == j    ) ? seg3 : v;
        v = (c == j + 1) ? seg2 : v;
        v = (c == j + 2) ? seg1 : v;
        v = (c == j + 3) ? seg0 : v;
        bs[j] = v;
    }
}

__device__ __forceinline__ float silu_f(float v) { return v / (1.0f + expf(-v)); }

// ---------------------------------------------------------------------------
// Merged prep kernel (R7 structure): expand1 + fusew1 + fusew2 in one launch.
// ---------------------------------------------------------------------------
#define E1_BLOCKS (B_SZ * (D_IN / 2) / 256)      // 40960
#define F1_BLOCKS (D_HID * D_IN / 256)            // 2560
#define F2_BLOCKS (N2PAD * D_HID / 256)           // 512
#define PREP_BLOCKS (E1_BLOCKS + F1_BLOCKS + F2_BLOCKS)

__global__ __launch_bounds__(256) void prep_kernel(
    const float* __restrict__ x,
    const float* __restrict__ bw1, const float* __restrict__ sw1,
    const float* __restrict__ sc1,
    const float* __restrict__ bw2, const float* __restrict__ sw2,
    const float* __restrict__ sc2)
{
    const int blk = blockIdx.x;
    if (blk < E1_BLOCKS) {
        // ---- expand1: 2 features per thread, __half2 stores ----
        int idx = blk * 256 + threadIdx.x;
        int b  = idx / (D_IN / 2);
        int i2 = (idx - b * (D_IN / 2)) * 2;
        float2 v = *reinterpret_cast<const float2*>(x + (size_t)b * D_IN + i2);
        float bs0[6], bs1[6];
        kan_bases(v.x, bs0);
        kan_bases(v.y, bs1);
        size_t base = (size_t)b * K1 + i2;
        *reinterpret_cast<__half2*>(&g_A1[base]) =
            __floats2half2_rn(silu_f(v.x), silu_f(v.y));
#pragma unroll
        for (int j = 0; j < 6; ++j)
            *reinterpret_cast<__half2*>(&g_A1[base + (size_t)(j + 1) * D_IN]) =
                __floats2half2_rn(bs0[j], bs1[j]);
    } else if (blk < E1_BLOCKS + F1_BLOCKS) {
        // ---- fusew1 ----
        int idx = (blk - E1_BLOCKS) * 256 + threadIdx.x;
        int o = idx / D_IN;
        int i = idx - o * D_IN;
        size_t base = (size_t)o * K1 + i;
        g_W1[base] = __float2half(bw1[idx]);
        float s = sc1[idx];
#pragma unroll
        for (int j = 0; j < 6; ++j)
            g_W1[base + (size_t)(j + 1) * D_IN] =
                __float2half(sw1[(size_t)idx * 6 + j] * s);
    } else {
        // ---- fusew2 (zero-padded rows o >= D_OUT) ----
        int idx = (blk - E1_BLOCKS - F1_BLOCKS) * 256 + threadIdx.x;
        int o = idx / D_HID;
        int c = idx - o * D_HID;
        size_t base = (size_t)o * K2 + c;
        if (o < D_OUT) {
            size_t widx = (size_t)o * D_HID + c;
            g_W2[base] = __float2half(bw2[widx]);
            float s = sc2[widx];
#pragma unroll
            for (int j = 0; j < 6; ++j)
                g_W2[base + (size_t)(j + 1) * D_HID] =
                    __float2half(sw2[widx * 6 + j] * s);
        } else {
            g_W2[base] = __float2half(0.0f);
#pragma unroll
            for (int j = 0; j < 6; ++j)
                g_W2[base + (size_t)(j + 1) * D_HID] = __float2half(0.0f);
        }
    }
}

// ---------------------------------------------------------------------------
// LayerNorm + expansion (R7 structure): block per row, thread t -> cols 2t,2t+1
// ---------------------------------------------------------------------------
__global__ __launch_bounds__(256) void ln_expand2_kernel(
    const float* __restrict__ gamma, const float* __restrict__ beta)
{
    int row = blockIdx.x;
    int t = threadIdx.x;
    const float* hr = g_h + (size_t)row * D_HID;
    float2 v = *reinterpret_cast<const float2*>(hr + 2 * t);

    __shared__ float red[8];
    float s = v.x + v.y;
#pragma unroll
    for (int o = 16; o; o >>= 1) s += __shfl_down_sync(0xffffffffu, s, o);
    if ((t & 31) == 0) red[t >> 5] = s;
    __syncthreads();
    float tot = 0.0f;
#pragma unroll
    for (int i = 0; i < 8; ++i) tot += red[i];
    float mean = tot * (1.0f / (float)D_HID);
    __syncthreads();

    float d0 = v.x - mean, d1 = v.y - mean;
    float q = d0 * d0 + d1 * d1;
#pragma unroll
    for (int o = 16; o; o >>= 1) q += __shfl_down_sync(0xffffffffu, q, o);
    if ((t & 31) == 0) red[t >> 5] = q;
    __syncthreads();
    float qt = 0.0f;
#pragma unroll
    for (int i = 0; i < 8; ++i) qt += red[i];
    float inv = rsqrtf(qt * (1.0f / (float)D_HID) + 1e-5f);

    const int c = 2 * t;
    float y0 = d0 * inv * gamma[c]     + beta[c];
    float y1 = d1 * inv * gamma[c + 1] + beta[c + 1];
    float bs0[6], bs1[6];
    kan_bases(y0, bs0);
    kan_bases(y1, bs1);
    size_t base = (size_t)row * K2 + c;
    *reinterpret_cast<__half2*>(&g_A2[base]) =
        __floats2half2_rn(silu_f(y0), silu_f(y1));
#pragma unroll
    for (int j = 0; j < 6; ++j)
        *reinterpret_cast<__half2*>(&g_A2[base + (size_t)(j + 1) * D_HID]) =
            __floats2half2_rn(bs0[j], bs1[j]);
}

// ---------------------------------------------------------------------------
// HMMA GEMM (frozen R5/R7 config — at the mma.sync instruction ceiling):
// Block 128x128x64, 512 threads (16 warps = 4M x 4N), warp tile 32x32.
// 32 warps/SM at 2 CTAs/SM. 3-stage cp.async ring. 144B smem rows.
// ---------------------------------------------------------------------------
#define BM 128
#define BN 128
#define BK 64
#define ROWB 144u
#define STG_B (uint32_t)((BM + BN) * ROWB)   // 36864 B
#define NSTG 3

template <int L>
__global__ __launch_bounds__(512, 2) void gemm_hmma(float* __restrict__ Cparam) {
    constexpr int KK = (L == 1) ? K1 : K2;
    constexpr int NV = (L == 1) ? D_HID : D_OUT;
    constexpr int KT = KK / BK;

    const __half* __restrict__ A  = (L == 1) ? g_A1 : g_A2;
    const __half* __restrict__ Bw = (L == 1) ? g_W1 : g_W2;
    float* __restrict__ C         = (L == 1) ? g_h  : Cparam;

    extern __shared__ __half smh[];
    const uint32_t sbase = (uint32_t)__cvta_generic_to_shared(smh);

    const int tid  = threadIdx.x;
    const int warp = tid >> 5;
    const int lane = tid & 31;
    const int wm = (warp & 3) * 32;
    const int wn = (warp >> 2) * 32;
    const int mb = blockIdx.y;
    const int nb = blockIdx.x;

    const __half* Abase = A  + (size_t)(mb * BM) * KK;
    const __half* Bbase = Bw + (size_t)(nb * BN) * KK;

    auto issue = [&](int kt) {
        const uint32_t sb = sbase + (uint32_t)(kt % NSTG) * STG_B;
#pragma unroll
        for (int i = 0; i < 2; ++i) {
            const int idx = tid + i * 512;
            const int r = idx >> 3, c = idx & 7;
            const void* src = Abase + (size_t)r * KK + kt * BK + c * 8;
            const uint32_t dst = sb + (uint32_t)r * ROWB + (uint32_t)c * 16u;
            asm volatile("cp.async.cg.shared.global [%0], [%1], 16;"
                         :: "r"(dst), "l"(src));
        }
#pragma unroll
        for (int i = 0; i < 2; ++i) {
            const int idx = tid + i * 512;
            const int r = idx >> 3, c = idx & 7;
            const void* src = Bbase + (size_t)r * KK + kt * BK + c * 8;
            const uint32_t dst = sb + (uint32_t)BM * ROWB
                               + (uint32_t)r * ROWB + (uint32_t)c * 16u;
            asm volatile("cp.async.cg.shared.global [%0], [%1], 16;"
                         :: "r"(dst), "l"(src));
        }
        asm volatile("cp.async.commit_group;" ::: "memory");
    };

    float acc[2][4][4] = {};

    issue(0); issue(1);

    const int lrow = lane & 15;
    const int lcb  = (lane >> 4) * 8;

#pragma unroll 1
    for (int kt = 0; kt < KT; ++kt) {
        if (kt + 1 < KT) asm volatile("cp.async.wait_group 1;" ::: "memory");
        else             asm volatile("cp.async.wait_group 0;" ::: "memory");
        __syncthreads();
        if (kt + 2 < KT) issue(kt + 2);

        const uint32_t sb = sbase + (uint32_t)(kt % NSTG) * STG_B;
#pragma unroll
        for (int ks = 0; ks < 4; ++ks) {
            uint32_t a[2][4];
            uint32_t bq[2][4];
#pragma unroll
            for (int mt = 0; mt < 2; ++mt) {
                const uint32_t addr = sb + (uint32_t)(wm + mt * 16 + lrow) * ROWB
                                    + (uint32_t)(ks * 16 + lcb) * 2u;
                asm volatile("ldmatrix.sync.aligned.m8n8.x4.shared.b16 {%0,%1,%2,%3}, [%4];"
                             : "=r"(a[mt][0]), "=r"(a[mt][1]), "=r"(a[mt][2]), "=r"(a[mt][3])
                             : "r"(addr));
            }
#pragma unroll
            for (int np = 0; np < 2; ++np) {
                const uint32_t addr = sb + (uint32_t)BM * ROWB
                                    + (uint32_t)(wn + np * 16 + lrow) * ROWB
                                    + (uint32_t)(ks * 16 + lcb) * 2u;
                asm volatile("ldmatrix.sync.aligned.m8n8.x4.shared.b16 {%0,%1,%2,%3}, [%4];"
                             : "=r"(bq[np][0]), "=r"(bq[np][1]), "=r"(bq[np][2]), "=r"(bq[np][3])
                             : "r"(addr));
            }
#pragma unroll
            for (int mt = 0; mt < 2; ++mt) {
#pragma unroll
                for (int nt = 0; nt < 4; ++nt) {
                    const int np = nt >> 1, pp = nt & 1;
                    asm volatile(
                        "mma.sync.aligned.m16n8k16.row.col.f32.f16.f16.f32 "
                        "{%0,%1,%2,%3}, {%4,%5,%6,%7}, {%8,%9}, {%0,%1,%2,%3};"
                        : "+f"(acc[mt][nt][0]), "+f"(acc[mt][nt][1]),
                          "+f"(acc[mt][nt][2]), "+f"(acc[mt][nt][3])
                        : "r"(a[mt][0]), "r"(a[mt][1]), "r"(a[mt][2]), "r"(a[mt][3]),
                          "r"(bq[np][pp]), "r"(bq[np][pp + 2]));
                }
            }
        }
    }

    // ---- epilogue ----
    const int gr = lane >> 2;
    const int gc = (lane & 3) * 2;
#pragma unroll
    for (int mt = 0; mt < 2; ++mt) {
#pragma unroll
        for (int nt = 0; nt < 4; ++nt) {
            const int row = mb * BM + wm + mt * 16 + gr;
            const int col = nb * BN + wn + nt * 8 + gc;
            float* cp = C + (size_t)row * NV;
            if (NV % BN == 0) {
                cp[col]     = acc[mt][nt][0];
                cp[col + 1] = acc[mt][nt][1];
                cp += (size_t)8 * NV;
                cp[col]     = acc[mt][nt][2];
                cp[col + 1] = acc[mt][nt][3];
            } else {
                if (col < NV)     cp[col]     = acc[mt][nt][0];
                if (col + 1 < NV) cp[col + 1] = acc[mt][nt][1];
                cp += (size_t)8 * NV;
                if (col < NV)     cp[col]     = acc[mt][nt][2];
                if (col + 1 < NV) cp[col + 1] = acc[mt][nt][3];
            }
        }
    }
}

// ---------------------------------------------------------------------------
// Launch
// ---------------------------------------------------------------------------
#define GEMM_SMEM (NSTG * (int)STG_B)   // 110592 B

extern "C" void kernel_launch(void* const* d_in, const int* in_sizes, int n_in,
                              void* d_out, int out_size) {
    (void)in_sizes; (void)n_in; (void)out_size;
    const float* x   = (const float*)d_in[0];
    const float* bw1 = (const float*)d_in[1];
    const float* sw1 = (const float*)d_in[2];
    const float* sc1 = (const float*)d_in[3];
    const float* ga  = (const float*)d_in[4];
    const float* be  = (const float*)d_in[5];
    const float* bw2 = (const float*)d_in[6];
    const float* sw2 = (const float*)d_in[7];
    const float* sc2 = (const float*)d_in[8];
    float* out = (float*)d_out;

    cudaFuncSetAttribute(gemm_hmma<1>,
                         cudaFuncAttributeMaxDynamicSharedMemorySize, GEMM_SMEM);
    cudaFuncSetAttribute(gemm_hmma<2>,
                         cudaFuncAttributeMaxDynamicSharedMemorySize, GEMM_SMEM);

    // One merged prep launch: expand1 + fusew1 + fusew2
    prep_kernel<<<PREP_BLOCKS, 256>>>(x, bw1, sw1, sc1, bw2, sw2, sc2);

    // GEMM1: 512 CTAs (4 x 128)
    gemm_hmma<1><<<dim3(4, 128), 512, GEMM_SMEM>>>(nullptr);

    ln_expand2_kernel<<<B_SZ, 256>>>(ga, be);

    // GEMM2: 256 CTAs (2 x 128)
    gemm_hmma<2><<<dim3(2, 128), 512, GEMM_SMEM>>>(out);
}